// round 4
// baseline (speedup 1.0000x reference)
#include <cuda_runtime.h>
#include <cuda_bf16.h>
#include <cstdint>

// out[m, r, t] = X0[r] + t * fl(dt * dXdt[r]),  m=0 -> S, m=1 -> I
// Closed form matches jax associative_scan cumsum to ~2e-7 (verified R2).
//
// R3: stage 16KB tiles in SMEM (STS.128) and drain via TMA bulk stores
// (cp.async.bulk shared::cta -> global), double-buffered. Bypasses the
// per-SM STG/L1 store path that capped R2 at 40% of LTS throughput.

#define NROWS 13

static constexpr int TILE_ELEMS = 4096;   // 16 KB per buffer
static constexpr int THREADS    = 256;
static constexpr int BLOCKS_X   = 40;     // 40*26 = 1040 blocks ~= 7/SM, 1 wave

__device__ __forceinline__ void compute_step_x0(
    int m, int r,
    const float* __restrict__ S0, const float* __restrict__ E0,
    const float* __restrict__ I0, const float* __restrict__ L,
    float b, float g, float K, float Ki, float h,
    float& step, float& x0)
{
    float acc = 0.0f;
    if (m == 0) {
        #pragma unroll
        for (int c = 0; c < NROWS; ++c) acc = fmaf(L[r * NROWS + c], S0[c], acc);
        const float dS = -K * acc - b * E0[r] * S0[r] - g * I0[r] * S0[r];
        step = h * dS;
        x0   = S0[r];
    } else {
        #pragma unroll
        for (int c = 0; c < NROWS; ++c) acc = fmaf(L[r * NROWS + c], I0[c], acc);
        const float dI = -Ki * acc + 0.2f * E0[r] - 0.01f * I0[r];
        step = h * dI;
        x0   = I0[r];
    }
}

// ---------------- TMA-store path (nt % 4 == 0) ----------------
__global__ void __launch_bounds__(THREADS)
sei_tma_kernel(const float* __restrict__ S0,
               const float* __restrict__ E0,
               const float* __restrict__ I0,
               const float* __restrict__ L,
               const float* __restrict__ beta_p,
               const float* __restrict__ gamma_p,
               const float* __restrict__ K_p,
               const float* __restrict__ Ki_p,
               const float* __restrict__ dt_p,
               float* __restrict__ out,
               int nt)
{
    __shared__ __align__(128) float buf[2][TILE_ELEMS];
    __shared__ float s_step, s_x0;

    const int y = blockIdx.y;            // y = m*13 + r
    const int m = (y >= NROWS) ? 1 : 0;
    const int r = y - m * NROWS;

    if (threadIdx.x == 0) {
        float step, x0;
        compute_step_x0(m, r, S0, E0, I0, L,
                        *beta_p, *gamma_p, *K_p, *Ki_p, *dt_p, step, x0);
        s_step = step;
        s_x0   = x0;
    }
    __syncthreads();

    const float step = s_step;
    const float x0   = s_x0;
    float* __restrict__ row = out + (size_t)y * (size_t)nt;

    const int tiles = (nt + TILE_ELEMS - 1) / TILE_ELEMS;
    int issued = 0;
    int bsel   = 0;

    for (int tile = blockIdx.x; tile < tiles; tile += BLOCKS_X) {
        const int base = tile * TILE_ELEMS;        // element offset within row
        const int n    = min(TILE_ELEMS, nt - base);  // n % 4 == 0 in this path

        // Reclaim the buffer used two tiles ago (keep <=1 group's reads pending)
        if (issued >= 2) {
            if (threadIdx.x == 0)
                asm volatile("cp.async.bulk.wait_group.read 1;" ::: "memory");
            __syncthreads();
        }

        float* __restrict__ b = buf[bsel];

        #pragma unroll
        for (int k = 0; k < TILE_ELEMS / (THREADS * 4); ++k) {  // 4 float4s/thread
            const int e = (threadIdx.x + k * THREADS) * 4;
            if (e < n) {
                const float tf = (float)(base + e);
                float4 v;
                v.x = fmaf(tf,        step, x0);
                v.y = fmaf(tf + 1.0f, step, x0);
                v.z = fmaf(tf + 2.0f, step, x0);
                v.w = fmaf(tf + 3.0f, step, x0);
                *reinterpret_cast<float4*>(b + e) = v;
            }
        }
        __syncthreads();

        if (threadIdx.x == 0) {
            // Order the generic-proxy STS above against the async proxy.
            asm volatile("fence.proxy.async.shared::cta;" ::: "memory");
            const uint32_t saddr = (uint32_t)__cvta_generic_to_shared(b);
            asm volatile(
                "cp.async.bulk.global.shared::cta.bulk_group [%0], [%1], %2;"
                :: "l"(row + base), "r"(saddr), "r"((uint32_t)(n * 4))
                : "memory");
            asm volatile("cp.async.bulk.commit_group;" ::: "memory");
        }
        issued++;
        bsel ^= 1;
    }

    // Drain all pending bulk stores before the CTA exits.
    if (threadIdx.x == 0)
        asm volatile("cp.async.bulk.wait_group.read 0;" ::: "memory");
}

// ---------------- scalar STG fallback (any nt) ----------------
__global__ void __launch_bounds__(256)
sei_fill_scalar(const float* __restrict__ S0,
                const float* __restrict__ E0,
                const float* __restrict__ I0,
                const float* __restrict__ L,
                const float* __restrict__ beta_p,
                const float* __restrict__ gamma_p,
                const float* __restrict__ K_p,
                const float* __restrict__ Ki_p,
                const float* __restrict__ dt_p,
                float* __restrict__ out,
                int nt)
{
    const int y = blockIdx.y;
    const int m = (y >= NROWS) ? 1 : 0;
    const int r = y - m * NROWS;

    __shared__ float s_step, s_x0;
    if (threadIdx.x == 0) {
        float step, x0;
        compute_step_x0(m, r, S0, E0, I0, L,
                        *beta_p, *gamma_p, *K_p, *Ki_p, *dt_p, step, x0);
        s_step = step;
        s_x0   = x0;
    }
    __syncthreads();

    const float step = s_step;
    const float x0   = s_x0;
    float* __restrict__ row = out + (long long)y * (long long)nt;

    const int elems_per_block = blockDim.x * 16;
    const int t_base = blockIdx.x * elems_per_block;
    #pragma unroll
    for (int j = 0; j < 16; ++j) {
        const int t = t_base + j * blockDim.x + threadIdx.x;
        if (t < nt) row[t] = fmaf((float)t, step, x0);
    }
}

extern "C" void kernel_launch(void* const* d_in, const int* in_sizes, int n_in,
                              void* d_out, int out_size)
{
    const float* S0   = (const float*)d_in[0];
    const float* E0   = (const float*)d_in[1];
    const float* I0   = (const float*)d_in[2];
    const float* L    = (const float*)d_in[3];
    const float* beta = (const float*)d_in[4];
    const float* gam  = (const float*)d_in[5];
    const float* K    = (const float*)d_in[6];
    const float* Ki   = (const float*)d_in[7];
    const float* dt   = (const float*)d_in[8];

    const int nt = out_size / (2 * NROWS);
    float* out = (float*)d_out;

    if ((nt & 3) == 0 && nt >= TILE_ELEMS) {
        dim3 grid(BLOCKS_X, 2 * NROWS, 1);
        dim3 block(THREADS, 1, 1);
        sei_tma_kernel<<<grid, block>>>(S0, E0, I0, L, beta, gam, K, Ki, dt, out, nt);
    } else {
        const int threads = 256;
        const int elems_per_block = threads * 16;
        dim3 grid((nt + elems_per_block - 1) / elems_per_block, 2 * NROWS, 1);
        sei_fill_scalar<<<grid, threads>>>(S0, E0, I0, L, beta, gam, K, Ki, dt, out, nt);
    }
}

// round 5
// speedup vs baseline: 1.0025x; 1.0025x over previous
#include <cuda_runtime.h>
#include <cuda_bf16.h>

// out[m, r, t] = X0[r] + t * fl(dt * dXdt[r]),  m=0 -> S, m=1 -> I
// Closed form matches jax associative_scan cumsum to ~2e-7 (verified R2/R3).
//
// R4: back to direct STG.128 (R3 showed the SMEM+TMA path is not faster:
// LTS cap is path-independent). Maximize per-warp outstanding stores:
// 8 front-batched STG.128 per thread, 512-thread CTAs, single wave.

#define NROWS 13

static constexpr int THREADS   = 512;
static constexpr int VPT       = 8;                      // float4s per thread
static constexpr int EPB       = THREADS * VPT * 4;      // 16384 elems / CTA

__device__ __forceinline__ void compute_step_x0(
    int m, int r,
    const float* __restrict__ S0, const float* __restrict__ E0,
    const float* __restrict__ I0, const float* __restrict__ L,
    float b, float g, float K, float Ki, float h,
    float& step, float& x0)
{
    float acc = 0.0f;
    if (m == 0) {
        #pragma unroll
        for (int c = 0; c < NROWS; ++c) acc = fmaf(L[r * NROWS + c], S0[c], acc);
        const float dS = -K * acc - b * E0[r] * S0[r] - g * I0[r] * S0[r];
        step = h * dS;
        x0   = S0[r];
    } else {
        #pragma unroll
        for (int c = 0; c < NROWS; ++c) acc = fmaf(L[r * NROWS + c], I0[c], acc);
        const float dI = -Ki * acc + 0.2f * E0[r] - 0.01f * I0[r];
        step = h * dI;
        x0   = I0[r];
    }
}

__global__ void __launch_bounds__(THREADS)
sei_fill_v4(const float* __restrict__ S0,
            const float* __restrict__ E0,
            const float* __restrict__ I0,
            const float* __restrict__ L,
            const float* __restrict__ beta_p,
            const float* __restrict__ gamma_p,
            const float* __restrict__ K_p,
            const float* __restrict__ Ki_p,
            const float* __restrict__ dt_p,
            float* __restrict__ out,
            int nt)
{
    const int y = blockIdx.y;            // y = m*13 + r
    const int m = (y >= NROWS) ? 1 : 0;
    const int r = y - m * NROWS;

    __shared__ float s_step, s_x0;
    if (threadIdx.x == 0) {
        float step, x0;
        compute_step_x0(m, r, S0, E0, I0, L,
                        *beta_p, *gamma_p, *K_p, *Ki_p, *dt_p, step, x0);
        s_step = step;
        s_x0   = x0;
    }
    __syncthreads();

    const float step = s_step;
    const float x0   = s_x0;
    float* __restrict__ row = out + (long long)y * (long long)nt;

    const int t_base = blockIdx.x * EPB;

    if (t_base + EPB <= nt) {
        // Full tile: compute all 8 float4s, then fire 8 back-to-back STG.128.
        float4 v[VPT];
        int    off[VPT];
        #pragma unroll
        for (int j = 0; j < VPT; ++j) {
            const int t0 = t_base + (j * THREADS + threadIdx.x) * 4;
            off[j] = t0;
            const float tf = (float)t0;
            v[j].x = fmaf(tf,        step, x0);
            v[j].y = fmaf(tf + 1.0f, step, x0);
            v[j].z = fmaf(tf + 2.0f, step, x0);
            v[j].w = fmaf(tf + 3.0f, step, x0);
        }
        #pragma unroll
        for (int j = 0; j < VPT; ++j)
            *reinterpret_cast<float4*>(row + off[j]) = v[j];
    } else {
        // Tail tile: vector where possible, scalar at the very end.
        #pragma unroll
        for (int j = 0; j < VPT; ++j) {
            const int t0 = t_base + (j * THREADS + threadIdx.x) * 4;
            if (t0 + 3 < nt) {
                const float tf = (float)t0;
                float4 v4;
                v4.x = fmaf(tf,        step, x0);
                v4.y = fmaf(tf + 1.0f, step, x0);
                v4.z = fmaf(tf + 2.0f, step, x0);
                v4.w = fmaf(tf + 3.0f, step, x0);
                *reinterpret_cast<float4*>(row + t0) = v4;
            } else {
                for (int t = t0; t < nt; ++t)
                    row[t] = fmaf((float)t, step, x0);
            }
        }
    }
}

extern "C" void kernel_launch(void* const* d_in, const int* in_sizes, int n_in,
                              void* d_out, int out_size)
{
    const float* S0   = (const float*)d_in[0];
    const float* E0   = (const float*)d_in[1];
    const float* I0   = (const float*)d_in[2];
    const float* L    = (const float*)d_in[3];
    const float* beta = (const float*)d_in[4];
    const float* gam  = (const float*)d_in[5];
    const float* K    = (const float*)d_in[6];
    const float* Ki   = (const float*)d_in[7];
    const float* dt   = (const float*)d_in[8];

    const int nt = out_size / (2 * NROWS);
    float* out = (float*)d_out;

    dim3 grid((nt + EPB - 1) / EPB, 2 * NROWS, 1);
    dim3 block(THREADS, 1, 1);
    sei_fill_v4<<<grid, block>>>(S0, E0, I0, L, beta, gam, K, Ki, dt, out, nt);
}